// round 6
// baseline (speedup 1.0000x reference)
#include <cuda_runtime.h>
#include <cuda_bf16.h>
#include <cstdint>

// SparseDenseMatMul: out[M,64] = segment_sum(vals[:,None] * A[cols], rows)
// Inputs: vals f32[NNZ], A f32[K,64], rows i32[NNZ], cols i32[NNZ]; out f32[M*64]
//
// R4 profile: L1tex 72.7% busy, ~17 wavefronts/edge -- the RED.128 atomics
// dominate. This version builds a CSR on device (count -> scan -> scatter)
// and reduces each row with one warp, register accumulation, plain stores.
// No output atomics, no output memset (every element overwritten).

#define M_ROWS   100000
#define NNZ_CAP  1600000
#define VEC_PER_ROW 16   // 64 cols / 4

__device__ int    g_start[M_ROWS + 1];   // row start offsets (CSR)
__device__ int    g_cursor[M_ROWS];      // counts, then running cursors
__device__ float2 g_csr[NNZ_CAP];        // (val, bitcast col) in CSR order

// ---- phase 0: zero counters ----
__global__ __launch_bounds__(256) void zero_kernel(int m)
{
    int i = blockIdx.x * blockDim.x + threadIdx.x;
    if (i < m) g_cursor[i] = 0;
}

// ---- phase 1: count nnz per row (int4-vectorized) ----
__global__ __launch_bounds__(256) void count_kernel(const int* __restrict__ rows, int nnz)
{
    int t = blockIdx.x * blockDim.x + threadIdx.x;
    int base = t * 4;
    if (base + 3 < nnz) {
        int4 r = *reinterpret_cast<const int4*>(rows + base);
        atomicAdd(&g_cursor[r.x], 1);
        atomicAdd(&g_cursor[r.y], 1);
        atomicAdd(&g_cursor[r.z], 1);
        atomicAdd(&g_cursor[r.w], 1);
    } else {
        for (int e = base; e < nnz; e++) atomicAdd(&g_cursor[rows[e]], 1);
    }
}

// ---- phase 2: single-block exclusive scan over m counts ----
__global__ __launch_bounds__(1024) void scan_kernel(int m)
{
    __shared__ int s[1024];
    int tid = threadIdx.x;
    int chunk = (m + 1023) / 1024;
    int lo = tid * chunk;
    int hi = min(lo + chunk, m);

    int sum = 0;
    for (int i = lo; i < hi; i++) sum += g_cursor[i];
    s[tid] = sum;
    __syncthreads();

    // Hillis-Steele inclusive scan over 1024 partials
    #pragma unroll
    for (int off = 1; off < 1024; off <<= 1) {
        int t = 0;
        if (tid >= off) t = s[tid - off];
        __syncthreads();
        if (tid >= off) s[tid] += t;
        __syncthreads();
    }

    int run = s[tid] - sum;   // exclusive prefix for this thread's chunk
    for (int i = lo; i < hi; i++) {
        int c = g_cursor[i];
        g_start[i]  = run;
        g_cursor[i] = run;    // reset cursor to row start for scatter phase
        run += c;
    }
    if (tid == 1023) g_start[m] = s[1023];
}

// ---- phase 3: scatter (val, col) into CSR order ----
__global__ __launch_bounds__(256) void scatter_kernel(
    const float* __restrict__ vals,
    const int*   __restrict__ rows,
    const int*   __restrict__ cols,
    int nnz)
{
    int t = blockIdx.x * blockDim.x + threadIdx.x;
    int base = t * 4;
    if (base + 3 < nnz) {
        int4   r = *reinterpret_cast<const int4*>(rows + base);
        int4   c = *reinterpret_cast<const int4*>(cols + base);
        float4 v = *reinterpret_cast<const float4*>(vals + base);
        int p0 = atomicAdd(&g_cursor[r.x], 1);
        int p1 = atomicAdd(&g_cursor[r.y], 1);
        int p2 = atomicAdd(&g_cursor[r.z], 1);
        int p3 = atomicAdd(&g_cursor[r.w], 1);
        g_csr[p0] = make_float2(v.x, __int_as_float(c.x));
        g_csr[p1] = make_float2(v.y, __int_as_float(c.y));
        g_csr[p2] = make_float2(v.z, __int_as_float(c.z));
        g_csr[p3] = make_float2(v.w, __int_as_float(c.w));
    } else {
        for (int e = base; e < nnz; e++) {
            int p = atomicAdd(&g_cursor[rows[e]], 1);
            g_csr[p] = make_float2(vals[e], __int_as_float(cols[e]));
        }
    }
}

// ---- phase 4: one warp per row, register accumulation, plain stores ----
__global__ __launch_bounds__(256) void reduce_kernel(
    const float* __restrict__ A,
    float*       __restrict__ out,
    int m)
{
    int gwarp = (blockIdx.x * blockDim.x + threadIdx.x) >> 5;
    if (gwarp >= m) return;
    int lane = threadIdx.x & 31;
    int half = lane >> 4;      // which edge of the pair this lane works on
    int c    = lane & 15;      // which float4 of the 64-wide row

    int s0 = g_start[gwarp];
    int s1 = g_start[gwarp + 1];

    const float4* A4 = reinterpret_cast<const float4*>(A);
    float4 acc = make_float4(0.f, 0.f, 0.f, 0.f);

    for (int p = s0 + half; p < s1; p += 2) {
        float2 vc = g_csr[p];                 // broadcast within 16-lane group
        int col = __float_as_int(vc.y);
        float4 a = __ldg(&A4[(unsigned)col * VEC_PER_ROW + c]);
        acc.x += vc.x * a.x;
        acc.y += vc.x * a.y;
        acc.z += vc.x * a.z;
        acc.w += vc.x * a.w;
    }

    // combine the two halves (lanes i and i+16 share column group c=i)
    acc.x += __shfl_xor_sync(0xffffffffu, acc.x, 16);
    acc.y += __shfl_xor_sync(0xffffffffu, acc.y, 16);
    acc.z += __shfl_xor_sync(0xffffffffu, acc.z, 16);
    acc.w += __shfl_xor_sync(0xffffffffu, acc.w, 16);

    if (half == 0) {
        reinterpret_cast<float4*>(out)[(unsigned)gwarp * VEC_PER_ROW + c] = acc;
    }
}

extern "C" void kernel_launch(void* const* d_in, const int* in_sizes, int n_in,
                              void* d_out, int out_size)
{
    const float* vals = (const float*)d_in[0];
    const float* A    = (const float*)d_in[1];
    const int*   rows = (const int*)d_in[2];
    const int*   cols = (const int*)d_in[3];
    float*       out  = (float*)d_out;

    int nnz = in_sizes[0];
    int m   = out_size / 64;

    zero_kernel<<<(m + 255) / 256, 256>>>(m);

    int edge4 = (nnz + 3) / 4;
    count_kernel<<<(edge4 + 255) / 256, 256>>>(rows, nnz);

    scan_kernel<<<1, 1024>>>(m);

    scatter_kernel<<<(edge4 + 255) / 256, 256>>>(vals, rows, cols, nnz);

    // one warp per row
    long long threads = (long long)m * 32;
    reduce_kernel<<<(unsigned)((threads + 255) / 256), 256>>>(A, out, m);
}

// round 7
// speedup vs baseline: 2.6886x; 2.6886x over previous
#include <cuda_runtime.h>
#include <cuda_bf16.h>
#include <cstdint>

// SparseDenseMatMul: out[M,64] = segment_sum(vals[:,None] * A[cols], rows)
// Inputs: vals f32[NNZ], A f32[K,64], rows i32[NNZ], cols i32[NNZ]; out f32[M*64]
//
// R6 post-mortem: single-block scan_kernel with per-thread chunked (uncoalesced)
// access burned ~140us on one SM. Replaced with a coalesced 3-kernel scan.
// Rest of CSR pipeline (count -> scan -> scatter -> warp-per-row reduce) kept.

#define M_ROWS   100000
#define NNZ_CAP  1600000
#define VEC_PER_ROW 16            // 64 cols / 4
#define SCAN_BLK 256
#define NB_MAX   ((M_ROWS + SCAN_BLK - 1) / SCAN_BLK)   // 391

__device__ int    g_start[M_ROWS + 1];   // row start offsets (CSR)
__device__ int    g_cursor[M_ROWS];      // counts, then running cursors
__device__ int    g_bsum[NB_MAX];        // per-block sums
__device__ int    g_boff[NB_MAX];        // per-block exclusive offsets
__device__ float2 g_csr[NNZ_CAP];        // (val, bitcast col) in CSR order

// ---- phase 0: zero counters ----
__global__ __launch_bounds__(256) void zero_kernel(int m)
{
    int i = blockIdx.x * blockDim.x + threadIdx.x;
    if (i < m) g_cursor[i] = 0;
}

// ---- phase 1: count nnz per row (int4-vectorized) ----
__global__ __launch_bounds__(256) void count_kernel(const int* __restrict__ rows, int nnz)
{
    int t = blockIdx.x * blockDim.x + threadIdx.x;
    int base = t * 4;
    if (base + 3 < nnz) {
        int4 r = *reinterpret_cast<const int4*>(rows + base);
        atomicAdd(&g_cursor[r.x], 1);
        atomicAdd(&g_cursor[r.y], 1);
        atomicAdd(&g_cursor[r.z], 1);
        atomicAdd(&g_cursor[r.w], 1);
    } else {
        for (int e = base; e < nnz; e++) atomicAdd(&g_cursor[rows[e]], 1);
    }
}

// ---- phase 2a: per-block exclusive scan (coalesced), emit block sums ----
__global__ __launch_bounds__(SCAN_BLK) void scanA_kernel(int m)
{
    __shared__ int warp_tot[SCAN_BLK / 32];
    int i   = blockIdx.x * SCAN_BLK + threadIdx.x;
    int lane = threadIdx.x & 31;
    int wid  = threadIdx.x >> 5;

    int v = (i < m) ? g_cursor[i] : 0;

    // warp inclusive scan
    int s = v;
    #pragma unroll
    for (int off = 1; off < 32; off <<= 1) {
        int t = __shfl_up_sync(0xffffffffu, s, off);
        if (lane >= off) s += t;
    }
    if (lane == 31) warp_tot[wid] = s;
    __syncthreads();

    // scan the 8 warp totals (warp 0)
    if (wid == 0) {
        int wt = (lane < SCAN_BLK / 32) ? warp_tot[lane] : 0;
        int ws = wt;
        #pragma unroll
        for (int off = 1; off < SCAN_BLK / 32; off <<= 1) {
            int t = __shfl_up_sync(0xffffffffu, ws, off);
            if (lane >= off) ws += t;
        }
        if (lane < SCAN_BLK / 32) warp_tot[lane] = ws - wt;  // exclusive
    }
    __syncthreads();

    int excl = s - v + warp_tot[wid];     // block-local exclusive prefix
    if (i < m) g_start[i] = excl;

    if (threadIdx.x == SCAN_BLK - 1)
        g_bsum[blockIdx.x] = excl + v;    // block total
}

// ---- phase 2b: scan block sums (single block) ----
__global__ __launch_bounds__(512) void scanB_kernel(int nb, int m)
{
    __shared__ int s[512];
    int tid = threadIdx.x;
    int v = (tid < nb) ? g_bsum[tid] : 0;
    s[tid] = v;
    __syncthreads();
    #pragma unroll
    for (int off = 1; off < 512; off <<= 1) {
        int t = 0;
        if (tid >= off) t = s[tid - off];
        __syncthreads();
        if (tid >= off) s[tid] += t;
        __syncthreads();
    }
    if (tid < nb) g_boff[tid] = s[tid] - v;   // exclusive
    if (tid == 511) g_start[m] = s[511];      // total nnz
}

// ---- phase 2c: add block offsets; reset cursors to row starts ----
__global__ __launch_bounds__(SCAN_BLK) void scanC_kernel(int m)
{
    int i = blockIdx.x * SCAN_BLK + threadIdx.x;
    if (i < m) {
        int v = g_start[i] + g_boff[blockIdx.x];
        g_start[i]  = v;
        g_cursor[i] = v;
    }
}

// ---- phase 3: scatter (val, col) into CSR order ----
__global__ __launch_bounds__(256) void scatter_kernel(
    const float* __restrict__ vals,
    const int*   __restrict__ rows,
    const int*   __restrict__ cols,
    int nnz)
{
    int t = blockIdx.x * blockDim.x + threadIdx.x;
    int base = t * 4;
    if (base + 3 < nnz) {
        int4   r = *reinterpret_cast<const int4*>(rows + base);
        int4   c = *reinterpret_cast<const int4*>(cols + base);
        float4 v = *reinterpret_cast<const float4*>(vals + base);
        int p0 = atomicAdd(&g_cursor[r.x], 1);
        int p1 = atomicAdd(&g_cursor[r.y], 1);
        int p2 = atomicAdd(&g_cursor[r.z], 1);
        int p3 = atomicAdd(&g_cursor[r.w], 1);
        g_csr[p0] = make_float2(v.x, __int_as_float(c.x));
        g_csr[p1] = make_float2(v.y, __int_as_float(c.y));
        g_csr[p2] = make_float2(v.z, __int_as_float(c.z));
        g_csr[p3] = make_float2(v.w, __int_as_float(c.w));
    } else {
        for (int e = base; e < nnz; e++) {
            int p = atomicAdd(&g_cursor[rows[e]], 1);
            g_csr[p] = make_float2(vals[e], __int_as_float(cols[e]));
        }
    }
}

// ---- phase 4: one warp per row, register accumulation, plain stores ----
__global__ __launch_bounds__(256) void reduce_kernel(
    const float* __restrict__ A,
    float*       __restrict__ out,
    int m)
{
    int gwarp = (blockIdx.x * blockDim.x + threadIdx.x) >> 5;
    if (gwarp >= m) return;
    int lane = threadIdx.x & 31;
    int half = lane >> 4;      // which edge of the pair this lane works on
    int c    = lane & 15;      // which float4 of the 64-wide row

    int s0 = g_start[gwarp];
    int s1 = g_start[gwarp + 1];

    const float4* A4 = reinterpret_cast<const float4*>(A);
    float4 acc = make_float4(0.f, 0.f, 0.f, 0.f);

    for (int p = s0 + half; p < s1; p += 2) {
        float2 vc = g_csr[p];                 // broadcast within 16-lane group
        int col = __float_as_int(vc.y);
        float4 a = __ldg(&A4[(unsigned)col * VEC_PER_ROW + c]);
        acc.x += vc.x * a.x;
        acc.y += vc.x * a.y;
        acc.z += vc.x * a.z;
        acc.w += vc.x * a.w;
    }

    // combine the two halves (lanes i and i+16 share column group c=i)
    acc.x += __shfl_xor_sync(0xffffffffu, acc.x, 16);
    acc.y += __shfl_xor_sync(0xffffffffu, acc.y, 16);
    acc.z += __shfl_xor_sync(0xffffffffu, acc.z, 16);
    acc.w += __shfl_xor_sync(0xffffffffu, acc.w, 16);

    if (half == 0) {
        reinterpret_cast<float4*>(out)[(unsigned)gwarp * VEC_PER_ROW + c] = acc;
    }
}

extern "C" void kernel_launch(void* const* d_in, const int* in_sizes, int n_in,
                              void* d_out, int out_size)
{
    const float* vals = (const float*)d_in[0];
    const float* A    = (const float*)d_in[1];
    const int*   rows = (const int*)d_in[2];
    const int*   cols = (const int*)d_in[3];
    float*       out  = (float*)d_out;

    int nnz = in_sizes[0];
    int m   = out_size / 64;
    int nb  = (m + SCAN_BLK - 1) / SCAN_BLK;

    zero_kernel<<<(m + 255) / 256, 256>>>(m);

    int edge4 = (nnz + 3) / 4;
    count_kernel<<<(edge4 + 255) / 256, 256>>>(rows, nnz);

    scanA_kernel<<<nb, SCAN_BLK>>>(m);
    scanB_kernel<<<1, 512>>>(nb, m);
    scanC_kernel<<<nb, SCAN_BLK>>>(m);

    scatter_kernel<<<(edge4 + 255) / 256, 256>>>(vals, rows, cols, nnz);

    // one warp per row
    long long threads = (long long)m * 32;
    reduce_kernel<<<(unsigned)((threads + 255) / 256), 256>>>(A, out, m);
}